// round 4
// baseline (speedup 1.0000x reference)
#include <cuda_runtime.h>
#include <cstdint>
#include <cstddef>

// Problem constants
#define N_PTS  262144      // S1*T = 32*8192 points
#define KCODES 512
#define DIM    64
#define TILE_P 64
#define NTILES (N_PTS / TILE_P)   // 4096
#define TAU    1e-4f       // near-tie refinement threshold (>> ulp(64)=7.6e-6)

// Output layout (concatenated tuple, fp32)
static const size_t O_LOSS = 0;
static const size_t O_Q    = 1;
static const size_t O_PERP = 16777217;
static const size_t O_ENC  = 16777218;
static const size_t O_DIST = 150994946;
static const size_t O_IDX  = 285212674;

__device__ int    g_counts[512];
__device__ double g_loss;

static __device__ __forceinline__ unsigned long long pack2(float a, float b) {
    unsigned long long r;
    asm("mov.b64 %0, {%1, %2};" : "=l"(r) : "f"(a), "f"(b));
    return r;
}
static __device__ __forceinline__ void unpack2(unsigned long long v, float& a, float& b) {
    asm("mov.b64 {%0, %1}, %2;" : "=f"(a), "=f"(b) : "l"(v));
}
// Two independent IEEE fp32 FMAs per issue (sm_100+ packed math).
static __device__ __forceinline__ void fma2(unsigned long long& acc,
                                            unsigned long long a,
                                            unsigned long long b) {
    asm("fma.rn.f32x2 %0, %1, %2, %0;" : "+l"(acc) : "l"(a), "l"(b));
}
static __device__ __forceinline__ float lo32(unsigned long long v) {
    return __uint_as_float((unsigned)(v & 0xffffffffull));
}

// Shared memory layout (bytes):
//   [0,        131072)  e_t  : float[64][512]   embedding transposed (e_t[d][k])
//   [131072,   163840)  x2   : ull  [64][64]    x packed (v,v) per (d, point)
//   [163840,   165888)  esq  : float[512]       ||e_k||^2
//   [165888,   166144)  xsq  : float[64]        ||x_p||^2
#define SMEM_BYTES 166144

__global__ __launch_bounds__(256, 1)
void vq_main(const float* __restrict__ x, const float* __restrict__ emb,
             float* __restrict__ out)
{
    extern __shared__ char smem[];
    float*              e_t = (float*)smem;
    unsigned long long* x2  = (unsigned long long*)(smem + 131072);
    float*              esq = (float*)(smem + 163840);
    float*              xsq = (float*)(smem + 165888);

    const int tid  = threadIdx.x;
    const int lane = tid & 31;
    const int w    = tid >> 5;

    // ---- Load embedding, transposed into e_t[d][k] (once per CTA) ----
    for (int i = tid; i < KCODES * DIM; i += 256) {
        int k = i >> 6, d = i & 63;
        e_t[d * 512 + k] = emb[i];
    }
    __syncthreads();
    // ||e_k||^2: rounded squares, sequential sum d ascending
    for (int k = tid; k < KCODES; k += 256) {
        float s = 0.f;
        for (int d = 0; d < DIM; ++d) {
            float v  = e_t[d * 512 + k];
            s = __fadd_rn(s, __fmul_rn(v, v));
        }
        esq[k] = s;
    }
    __syncthreads();

    float* out_dist = out + O_DIST;
    float* out_enc  = out + O_ENC;
    float* out_idx  = out + O_IDX;

    for (int tile = blockIdx.x; tile < NTILES; tile += gridDim.x) {
        const int n0 = tile * TILE_P;

        // ---- Load x tile: x[d][n0+p], pack (v,v) into x2[d][p] ----
        for (int i = tid; i < TILE_P * DIM; i += 256) {
            int d = i >> 6, p = i & 63;
            float v = x[(size_t)d * N_PTS + (size_t)(n0 + p)];
            x2[d * 64 + p] = pack2(v, v);
        }
        __syncthreads();
        // ||x_p||^2: rounded squares, sequential sum d ascending
        if (tid < TILE_P) {
            float s = 0.f;
            for (int d = 0; d < DIM; ++d) {
                float v = lo32(x2[d * 64 + tid]);
                s = __fadd_rn(s, __fmul_rn(v, v));
            }
            xsq[tid] = s;
        }
        __syncthreads();

        const int pbase = w * 8;   // warp handles 8 points
        float bv1[8]; int bk1[8]; float bv2[8];
#pragma unroll
        for (int p = 0; p < 8; ++p) { bv1[p] = 3.0e38f; bk1[p] = 1 << 30; bv2[p] = 3.0e38f; }

        // Lane covers code pairs k = {(h*4+c)*64 + 2*lane, +1}, c=0..3, h=0..1
        for (int h = 0; h < 2; ++h) {
            unsigned long long acc[8][4];
#pragma unroll
            for (int p = 0; p < 8; ++p)
#pragma unroll
                for (int c = 0; c < 4; ++c) acc[p][c] = 0ull;

#pragma unroll 4
            for (int d = 0; d < DIM; ++d) {     // sequential fused-FMA dot, d ascending
                const unsigned long long* xd = x2 + d * 64 + pbase;
                unsigned long long xp[8];
#pragma unroll
                for (int p = 0; p < 8; ++p) xp[p] = xd[p];     // broadcast LDS.64
                const unsigned long long* ed =
                    (const unsigned long long*)(e_t + d * 512) + h * 128 + lane;
                unsigned long long ev[4];
#pragma unroll
                for (int c = 0; c < 4; ++c) ev[c] = ed[c * 32]; // conflict-free LDS.64
#pragma unroll
                for (int p = 0; p < 8; ++p)
#pragma unroll
                    for (int c = 0; c < 4; ++c) fma2(acc[p][c], xp[p], ev[c]);
            }

            // ---- Epilogue: distances + running top-2 ----
#pragma unroll
            for (int p = 0; p < 8; ++p) {
                const float xq = xsq[pbase + p];
                const size_t n = (size_t)(n0 + pbase + p);
                float2* drow = (float2*)(out_dist + n * 512);
#pragma unroll
                for (int c = 0; c < 4; ++c) {
                    const int j  = (h * 4 + c) * 32 + lane;
                    const int k0 = 2 * j;
                    float a, b; unpack2(acc[p][c], a, b);
                    float2 es = ((const float2*)esq)[j];
                    float d0 = __fsub_rn(__fadd_rn(xq, es.x), __fmul_rn(2.0f, a));
                    float d1 = __fsub_rn(__fadd_rn(xq, es.y), __fmul_rn(2.0f, b));
                    drow[j] = make_float2(d0, d1);
                    // top-2 update (best carries first-index tie-break)
                    if (d0 < bv1[p] || (d0 == bv1[p] && k0 < bk1[p]))
                        { bv2[p] = bv1[p]; bv1[p] = d0; bk1[p] = k0; }
                    else bv2[p] = fminf(bv2[p], d0);
                    if (d1 < bv1[p] || (d1 == bv1[p] && (k0 + 1) < bk1[p]))
                        { bv2[p] = bv1[p]; bv1[p] = d1; bk1[p] = k0 + 1; }
                    else bv2[p] = fminf(bv2[p], d1);
                }
            }
        }

        // ---- Per-point: warp top-2 reduce, optional precise refinement ----
#pragma unroll
        for (int p = 0; p < 8; ++p) {
            float v1 = bv1[p]; int k1 = bk1[p]; float v2 = bv2[p];
            for (int off = 16; off; off >>= 1) {
                float ov1 = __shfl_down_sync(0xffffffffu, v1, off);
                int   ok1 = __shfl_down_sync(0xffffffffu, k1, off);
                float ov2 = __shfl_down_sync(0xffffffffu, v2, off);
                if (ov1 < v1 || (ov1 == v1 && ok1 < k1)) {
                    v2 = fminf(v1, fminf(v2, ov2));
                    v1 = ov1; k1 = ok1;
                } else {
                    v2 = fminf(v2, fminf(ov1, ov2));
                }
            }
            v1 = __shfl_sync(0xffffffffu, v1, 0);
            k1 = __shfl_sync(0xffffffffu, k1, 0);
            v2 = __shfl_sync(0xffffffffu, v2, 0);

            int bk = k1;
            if (v2 - v1 < TAU) {
                // Near-tie: decide with correctly-rounded (double) dot products.
                const float xq = xsq[pbase + p];
                float bestdf = 3.0e38f; int bestk = 1 << 30;
                for (int h = 0; h < 2; ++h) {
#pragma unroll
                    for (int c = 0; c < 4; ++c) {
#pragma unroll
                        for (int half = 0; half < 2; ++half) {
                            const int k = (h * 4 + c) * 64 + 2 * lane + half;
                            // fp32 screen (sequential FMA, same as fast path)
                            float s = 0.f;
                            for (int d = 0; d < DIM; ++d)
                                s = __fmaf_rn(lo32(x2[d * 64 + pbase + p]),
                                              e_t[d * 512 + k], s);
                            float ds = __fsub_rn(__fadd_rn(xq, esq[k]),
                                                 __fmul_rn(2.0f, s));
                            if (ds <= v1 + TAU) {
                                double dd = 0.0;
                                for (int d = 0; d < DIM; ++d)
                                    dd = fma((double)lo32(x2[d * 64 + pbase + p]),
                                             (double)e_t[d * 512 + k], dd);
                                float df = __fsub_rn(__fadd_rn(xq, esq[k]),
                                                     __fmul_rn(2.0f, (float)dd));
                                if (df < bestdf || (df == bestdf && k < bestk))
                                    { bestdf = df; bestk = k; }
                            }
                        }
                    }
                }
                for (int off = 16; off; off >>= 1) {
                    float ov = __shfl_down_sync(0xffffffffu, bestdf, off);
                    int   ok = __shfl_down_sync(0xffffffffu, bestk, off);
                    if (ov < bestdf || (ov == bestdf && ok < bestk))
                        { bestdf = ov; bestk = ok; }
                }
                bk = __shfl_sync(0xffffffffu, bestk, 0);
            }

            const size_t n = (size_t)(n0 + pbase + p);
            if (lane == 0) {
                out_idx[n] = (float)bk;
                atomicAdd(&g_counts[bk], 1);
            }
            float2* erow = (float2*)(out_enc + n * 512);
#pragma unroll
            for (int j2 = 0; j2 < 8; ++j2) {
                int k0 = j2 * 64 + 2 * lane;
                erow[j2 * 32 + lane] =
                    make_float2(k0 == bk ? 1.f : 0.f, (k0 + 1) == bk ? 1.f : 0.f);
            }
        }
        __syncthreads();
    }
}

// quantized gather + straight-through + loss partial sums
__global__ __launch_bounds__(256)
void vq_quant(const float* __restrict__ x, const float* __restrict__ emb,
              const float* __restrict__ idxf, float* __restrict__ outq)
{
    const unsigned g = blockIdx.x * 256u + threadIdx.x;   // 0 .. 16777215
    const unsigned n = g & (N_PTS - 1);
    const unsigned d = g >> 18;
    const int k = (int)idxf[n];
    const float xv = x[g];
    const float q  = emb[k * 64 + d];
    const float diff = __fsub_rn(q, xv);       // (quantized - x), rounded
    outq[g] = __fadd_rn(xv, diff);             // straight-through value
    double v = (double)diff * (double)diff;
    for (int off = 16; off; off >>= 1) v += __shfl_down_sync(0xffffffffu, v, off);
    __shared__ double ws[8];
    if ((threadIdx.x & 31) == 0) ws[threadIdx.x >> 5] = v;
    __syncthreads();
    if (threadIdx.x == 0) {
        double s = 0.0;
        for (int i = 0; i < 8; ++i) s += ws[i];
        atomicAdd(&g_loss, s);
    }
}

__global__ void vq_zero()
{
    int t = threadIdx.x;
    if (t < 512) g_counts[t] = 0;
    if (t == 0)  g_loss = 0.0;
}

__global__ void vq_final(float* __restrict__ out)
{
    __shared__ double sh[512];
    int t = threadIdx.x;
    double p = (double)g_counts[t] * (1.0 / 262144.0);
    sh[t] = p * log(p + 1e-10);
    __syncthreads();
    for (int s = 256; s; s >>= 1) {
        if (t < s) sh[t] += sh[t + s];
        __syncthreads();
    }
    if (t == 0) {
        out[O_PERP] = (float)exp(-sh[0]);
        float m = (float)(g_loss * (1.0 / 16777216.0));
        out[O_LOSS] = m + 0.25f * m;   // q_latent + 0.25 * e_latent (identical means)
    }
}

extern "C" void kernel_launch(void* const* d_in, const int* in_sizes, int n_in,
                              void* d_out, int out_size)
{
    const float* x   = (const float*)d_in[0];   // (64, 32, 8192) fp32
    const float* emb = (const float*)d_in[1];   // (512, 64) fp32
    float* out = (float*)d_out;

    cudaFuncSetAttribute(vq_main, cudaFuncAttributeMaxDynamicSharedMemorySize, SMEM_BYTES);

    vq_zero<<<1, 512>>>();
    vq_main<<<148, 256, SMEM_BYTES>>>(x, emb, out);
    vq_quant<<<N_PTS * DIM / 256, 256>>>(x, emb, out + O_IDX, out + O_Q);
    vq_final<<<1, 512>>>(out);
}

// round 6
// speedup vs baseline: 1.2005x; 1.2005x over previous
#include <cuda_runtime.h>
#include <cstdint>
#include <cstddef>

// Problem constants
#define N_PTS  262144      // S1*T
#define KCODES 512
#define DIM    64
#define MT     256         // points per tile
#define NT     (N_PTS / MT)   // 1024 tiles
#define TAU    1e-4f
#define CANDM  2e-4f

// Output layout (concatenated tuple, fp32)
static const size_t O_LOSS = 0;
static const size_t O_Q    = 1;
static const size_t O_PERP = 16777217;
static const size_t O_ENC  = 16777218;
static const size_t O_DIST = 150994946;
static const size_t O_IDX  = 285212674;

__device__ int    g_counts[512];
__device__ double g_loss;

// ---- SMEM layout (bytes) ----
// XB  : float  [256][68]  x tile fp32 (padded stride 68)        69632
// ETF : u32    [512][68]  codebook tf32 bits ([code][k])       139264
// ESQ : float  [512]
// XSQ : float  [256]
// T2V1/T2K1/T2V2 : per-point top-2
// BK  : int [256], RED: double[8]
#define SM_XB   0
#define SM_ETF  69632
#define SM_ESQ  208896
#define SM_XSQ  210944
#define SM_T2V1 211968
#define SM_T2K1 212992
#define SM_T2V2 214016
#define SM_BK   215040
#define SM_RED  216064
#define SMEM_TOTAL 216128

static __device__ __forceinline__ uint32_t f2tf(float f) {
    uint32_t u;
    asm("cvt.rna.tf32.f32 %0, %1;" : "=r"(u) : "f"(f));
    return u;
}
static __device__ __forceinline__ void mma_tf32(float* d, const uint32_t* a,
                                                uint32_t b0, uint32_t b1) {
    asm volatile("mma.sync.aligned.m16n8k8.row.col.f32.tf32.tf32.f32 "
                 "{%0,%1,%2,%3}, {%4,%5,%6,%7}, {%8,%9}, {%0,%1,%2,%3};"
                 : "+f"(d[0]), "+f"(d[1]), "+f"(d[2]), "+f"(d[3])
                 : "r"(a[0]), "r"(a[1]), "r"(a[2]), "r"(a[3]), "r"(b0), "r"(b1));
}
// top-2 merge helper (first-index tie-break on best)
static __device__ __forceinline__ void t2merge(float& v1, int& k1, float& v2,
                                               float ov1, int ok1, float ov2) {
    if (ov1 < v1 || (ov1 == v1 && ok1 < k1)) {
        v2 = fminf(v1, fminf(v2, ov2));
        v1 = ov1; k1 = ok1;
    } else {
        v2 = fminf(v2, fminf(ov1, ov2));
    }
}

__global__ __launch_bounds__(256, 1)
void vq_tc(const float* __restrict__ x, const float* __restrict__ emb,
           float* __restrict__ out)
{
    extern __shared__ char smem[];
    float*    xb  = (float*)(smem + SM_XB);      // stride 68
    uint32_t* etf = (uint32_t*)(smem + SM_ETF);  // stride 68
    float*    esq = (float*)(smem + SM_ESQ);
    float*    xsq = (float*)(smem + SM_XSQ);
    float*    t2v1 = (float*)(smem + SM_T2V1);
    int*      t2k1 = (int*)(smem + SM_T2K1);
    float*    t2v2 = (float*)(smem + SM_T2V2);
    int*      bk_a = (int*)(smem + SM_BK);
    double*   red  = (double*)(smem + SM_RED);

    const int tid  = threadIdx.x;
    const int lane = tid & 31;
    const int w    = tid >> 5;
    const int gid  = lane >> 2;     // 0..7
    const int tg   = lane & 3;      // 0..3
    const int pbase = w * 32;       // warp owns 32 points

    // ---- Codebook -> tf32 bits in SMEM ([n][k], stride 68); esq (ref recipe) ----
    for (int i = tid; i < KCODES * DIM; i += 256) {
        int n = i >> 6, k = i & 63;
        etf[n * 68 + k] = f2tf(emb[i]);
    }
    for (int k = tid; k < KCODES; k += 256) {
        float s = 0.f;
        for (int d = 0; d < DIM; ++d) {
            float v = emb[k * 64 + d];
            s = __fadd_rn(s, __fmul_rn(v, v));
        }
        esq[k] = s;
    }
    __syncthreads();

    float* out_dist = out + O_DIST;
    double loss_acc = 0.0;

    for (int tile = blockIdx.x; tile < NT; tile += gridDim.x) {
        const int n0 = tile * MT;

        // ---- Load x tile into SMEM fp32 [p][d] (coalesced over n) ----
        for (int it = 0; it < 64; ++it) {
            int idx = it * 256 + tid;           // 16384 = 64 d * 256 p
            int d = idx >> 8, p = idx & 255;
            xb[p * 68 + d] = x[(size_t)d * N_PTS + n0 + p];
        }
        __syncthreads();
        // ||x_p||^2: reference recipe (rounded squares, sequential d)
        {
            float s = 0.f;
            for (int d = 0; d < DIM; ++d) {
                float v = xb[tid * 68 + d];
                s = __fadd_rn(s, __fmul_rn(v, v));
            }
            xsq[tid] = s;
        }
        __syncthreads();

        // per-warp top-2 state: [mb][half-row]
        float v1s[2][2], v2s[2][2]; int k1s[2][2];
#pragma unroll
        for (int mb = 0; mb < 2; ++mb)
#pragma unroll
            for (int hh = 0; hh < 2; ++hh)
                { v1s[mb][hh] = 3.0e38f; v2s[mb][hh] = 3.0e38f; k1s[mb][hh] = 1 << 30; }

        // ---- 8 passes of 64 codes; per pass: K=64 via 8 k-steps of mma ----
        for (int pass = 0; pass < 8; ++pass) {
            float acc[2][8][4];
#pragma unroll
            for (int mb = 0; mb < 2; ++mb)
#pragma unroll
                for (int nb = 0; nb < 8; ++nb)
#pragma unroll
                    for (int q = 0; q < 4; ++q) acc[mb][nb][q] = 0.f;

#pragma unroll
            for (int kk = 0; kk < 8; ++kk) {
                // A fragments for both m-blocks (rows pbase+mb*16+gid, +8)
                uint32_t afr[2][4];
#pragma unroll
                for (int mb = 0; mb < 2; ++mb) {
                    int r = pbase + mb * 16 + gid;
                    afr[mb][0] = f2tf(xb[r * 68 + kk * 8 + tg]);
                    afr[mb][1] = f2tf(xb[(r + 8) * 68 + kk * 8 + tg]);
                    afr[mb][2] = f2tf(xb[r * 68 + kk * 8 + tg + 4]);
                    afr[mb][3] = f2tf(xb[(r + 8) * 68 + kk * 8 + tg + 4]);
                }
                // B fragments for 8 n-blocks
                uint32_t b0[8], b1[8];
#pragma unroll
                for (int nb = 0; nb < 8; ++nb) {
                    int n = pass * 64 + nb * 8 + gid;
                    b0[nb] = etf[n * 68 + kk * 8 + tg];
                    b1[nb] = etf[n * 68 + kk * 8 + tg + 4];
                }
#pragma unroll
                for (int mb = 0; mb < 2; ++mb)
#pragma unroll
                    for (int nb = 0; nb < 8; ++nb)
                        mma_tf32(acc[mb][nb], afr[mb], b0[nb], b1[nb]);
            }

            // ---- Pass epilogue: dist + store + top-2 ----
#pragma unroll
            for (int mb = 0; mb < 2; ++mb) {
                const int r0 = pbase + mb * 16 + gid;
                const int r1 = r0 + 8;
                const float xq0 = xsq[r0], xq1 = xsq[r1];
                float* drow0 = out_dist + (size_t)(n0 + r0) * 512;
                float* drow1 = out_dist + (size_t)(n0 + r1) * 512;
#pragma unroll
                for (int nb = 0; nb < 8; ++nb) {
                    const int col = pass * 64 + nb * 8 + 2 * tg;
                    float2 es = *(float2*)(esq + col);
                    float d00 = __fsub_rn(__fadd_rn(xq0, es.x),
                                          __fmul_rn(2.0f, acc[mb][nb][0]));
                    float d01 = __fsub_rn(__fadd_rn(xq0, es.y),
                                          __fmul_rn(2.0f, acc[mb][nb][1]));
                    float d10 = __fsub_rn(__fadd_rn(xq1, es.x),
                                          __fmul_rn(2.0f, acc[mb][nb][2]));
                    float d11 = __fsub_rn(__fadd_rn(xq1, es.y),
                                          __fmul_rn(2.0f, acc[mb][nb][3]));
                    *(float2*)(drow0 + col) = make_float2(d00, d01);
                    *(float2*)(drow1 + col) = make_float2(d10, d11);
                    // ascending col order -> strict < keeps first index
                    if (d00 < v1s[mb][0]) { v2s[mb][0] = v1s[mb][0]; v1s[mb][0] = d00; k1s[mb][0] = col; }
                    else if (d00 < v2s[mb][0]) v2s[mb][0] = d00;
                    if (d01 < v1s[mb][0]) { v2s[mb][0] = v1s[mb][0]; v1s[mb][0] = d01; k1s[mb][0] = col + 1; }
                    else if (d01 < v2s[mb][0]) v2s[mb][0] = d01;
                    if (d10 < v1s[mb][1]) { v2s[mb][1] = v1s[mb][1]; v1s[mb][1] = d10; k1s[mb][1] = col; }
                    else if (d10 < v2s[mb][1]) v2s[mb][1] = d10;
                    if (d11 < v1s[mb][1]) { v2s[mb][1] = v1s[mb][1]; v1s[mb][1] = d11; k1s[mb][1] = col + 1; }
                    else if (d11 < v2s[mb][1]) v2s[mb][1] = d11;
                }
            }
        }

        // ---- Reduce top-2 across the 4 tg-lanes sharing each row ----
#pragma unroll
        for (int mb = 0; mb < 2; ++mb)
#pragma unroll
            for (int hh = 0; hh < 2; ++hh) {
                float v1 = v1s[mb][hh], v2 = v2s[mb][hh]; int k1 = k1s[mb][hh];
#pragma unroll
                for (int off = 1; off <= 2; off <<= 1) {
                    float ov1 = __shfl_xor_sync(0xffffffffu, v1, off);
                    int   ok1 = __shfl_xor_sync(0xffffffffu, k1, off);
                    float ov2 = __shfl_xor_sync(0xffffffffu, v2, off);
                    t2merge(v1, k1, v2, ov1, ok1, ov2);
                }
                if (tg == 0) {
                    int row = pbase + mb * 16 + hh * 8 + gid;
                    t2v1[row] = v1; t2k1[row] = k1; t2v2[row] = v2;
                }
            }
        __syncthreads();

        // ---- Per-point: fp64 refinement of near-ties, write idx ----
        {
            float m1 = t2v1[tid], m2 = t2v2[tid]; int bk = t2k1[tid];
            if (m2 - m1 < TAU) {
                const float* dr = out_dist + (size_t)(n0 + tid) * 512;
                const float mxq = xsq[tid];
                float bestdf = 3.0e38f; int bestk = 1 << 30;
                for (int k = 0; k < KCODES; ++k) {
                    if (dr[k] < m1 + CANDM) {
                        double dd = 0.0;
                        for (int d = 0; d < DIM; ++d)
                            dd = fma((double)xb[tid * 68 + d], (double)emb[k * 64 + d], dd);
                        float df = __fsub_rn(__fadd_rn(mxq, esq[k]),
                                             __fmul_rn(2.0f, (float)dd));
                        if (df < bestdf || (df == bestdf && k < bestk))
                            { bestdf = df; bestk = k; }
                    }
                }
                bk = bestk;
            }
            bk_a[tid] = bk;
            out[O_IDX + n0 + tid] = (float)bk;
            atomicAdd(&g_counts[bk], 1);
        }
        __syncthreads();

        // ---- Quantized (straight-through) + loss, layout [d][n] ----
        for (int it = 0; it < 64; ++it) {
            int idx = it * 256 + tid;
            int d = idx >> 8, p = idx & 255;
            int k = bk_a[p];
            float xv = xb[p * 68 + d];
            float qv = emb[k * 64 + d];
            float diff = __fsub_rn(qv, xv);
            out[O_Q + (size_t)d * N_PTS + n0 + p] = __fadd_rn(xv, diff);
            loss_acc += (double)diff * (double)diff;
        }

        // ---- One-hot encodings (one full row per iteration, coalesced) ----
        {
            float* encp = out + O_ENC;
            const int c0 = tid * 2;
            for (int p = 0; p < MT; ++p) {
                int k = bk_a[p];
                *(float2*)(encp + (size_t)(n0 + p) * 512 + c0) =
                    make_float2(c0 == k ? 1.f : 0.f, c0 + 1 == k ? 1.f : 0.f);
            }
        }
        __syncthreads();   // protect xb/bk before next tile
    }

    // ---- Loss reduce -> global ----
    for (int off = 16; off; off >>= 1)
        loss_acc += __shfl_down_sync(0xffffffffu, loss_acc, off);
    if (lane == 0) red[w] = loss_acc;
    __syncthreads();
    if (tid == 0) {
        double s = 0.0;
        for (int i = 0; i < 8; ++i) s += red[i];
        atomicAdd(&g_loss, s);
    }
}

__global__ void vq_zero()
{
    int t = threadIdx.x;
    if (t < 512) g_counts[t] = 0;
    if (t == 0)  g_loss = 0.0;
}

__global__ void vq_final(float* __restrict__ out)
{
    __shared__ double sh[512];
    int t = threadIdx.x;
    double p = (double)g_counts[t] * (1.0 / 262144.0);
    sh[t] = p * log(p + 1e-10);
    __syncthreads();
    for (int s = 256; s; s >>= 1) {
        if (t < s) sh[t] += sh[t + s];
        __syncthreads();
    }
    if (t == 0) {
        out[O_PERP] = (float)exp(-sh[0]);
        float m = (float)(g_loss * (1.0 / 16777216.0));
        out[O_LOSS] = m + 0.25f * m;   // q_latent + 0.25 * e_latent (identical means)
    }
}

extern "C" void kernel_launch(void* const* d_in, const int* in_sizes, int n_in,
                              void* d_out, int out_size)
{
    const float* x   = (const float*)d_in[0];   // (64, 32, 8192) fp32
    const float* emb = (const float*)d_in[1];   // (512, 64) fp32
    float* out = (float*)d_out;

    cudaFuncSetAttribute(vq_tc, cudaFuncAttributeMaxDynamicSharedMemorySize, SMEM_TOTAL);

    vq_zero<<<1, 512>>>();
    vq_tc<<<148, 256, SMEM_TOTAL>>>(x, emb, out);
    vq_final<<<1, 512>>>(out);
}